// round 6
// baseline (speedup 1.0000x reference)
#include <cuda_runtime.h>
#include <cuda_bf16.h>
#include <cstdint>

// ---------------- problem constants ----------------
#define BB     4
#define CC     64
#define H0     48
#define W0     48
#define QQ     16384
#define MROWS  (BB*QQ*4)     // 262144
#define HID    256
#define K0P    272           // layer-0 K (260) padded to multiple of 16

// ---------------- scratch ----------------
__device__ float g_feat [BB*CC*H0*W0];
__device__ float g_feat1[BB*CC*96*96];
__device__ float g_feat2[BB*CC*192*192];
__device__ float g_feat3[BB*CC*384*384];
__device__ float g_feat4[BB*CC*192*192];
__device__ float g_feat5[BB*CC*96*96];
__device__ float g_X  [(size_t)MROWS*K0P];
__device__ float g_H0b[(size_t)MROWS*HID];
__device__ float g_H1b[(size_t)MROWS*HID];
__device__ float g_Wt [256*K0P + 3*256*256];   // transposed weights [n][k]
__device__ float g_P  [(size_t)MROWS*3];
__device__ float g_area[MROWS];

// ================= conv kernels (unchanged, passing) =================
__global__ void enc_conv(const float* __restrict__ inp,
                         const float* __restrict__ w,
                         const float* __restrict__ b)
{
    int idx = blockIdx.x*256 + threadIdx.x;
    if (idx >= BB*CC*H0*W0) return;
    int x  = idx % W0;
    int y  = (idx / W0) % H0;
    int co = (idx / (H0*W0)) % CC;
    int bb = idx / (H0*W0*CC);
    float acc = b[co];
    const float* ib = inp + (size_t)bb*3*H0*W0;
    #pragma unroll
    for (int ci = 0; ci < 3; ci++) {
        #pragma unroll
        for (int ky = 0; ky < 3; ky++) {
            int yy = y + ky - 1;
            if (yy < 0 || yy >= H0) continue;
            #pragma unroll
            for (int kx = 0; kx < 3; kx++) {
                int xx = x + kx - 1;
                if (xx < 0 || xx >= W0) continue;
                acc += ib[ci*H0*W0 + yy*W0 + xx] * w[(co*3 + ci)*9 + ky*3 + kx];
            }
        }
    }
    g_feat[idx] = acc;
}

__global__ void up_conv_ps(const float* __restrict__ in, float* __restrict__ out,
                           int H, int W,
                           const float* __restrict__ w, const float* __restrict__ bias)
{
    __shared__ float s_in[8][18][18];
    __shared__ float s_w[4][8][9];
    int tx = threadIdx.x, ty = threadIdx.y, tid = ty*16 + tx;
    int x0 = blockIdx.x*16, y0 = blockIdx.y*16;
    int bb = blockIdx.z >> 6;
    int cog = blockIdx.z & 63;
    float acc[4] = {0.f,0.f,0.f,0.f};
    const float* inb = in + (size_t)bb*CC*H*W;

    for (int c0 = 0; c0 < CC; c0 += 8) {
        for (int i = tid; i < 8*18*18; i += 256) {
            int ci = i / 324, rem = i % 324, r = rem / 18, c = rem % 18;
            int y = y0 + r - 1, x = x0 + c - 1;
            float v = 0.f;
            if (y >= 0 && y < H && x >= 0 && x < W)
                v = inb[(size_t)(c0+ci)*H*W + y*W + x];
            s_in[ci][r][c] = v;
        }
        for (int i = tid; i < 288; i += 256) {
            int col = i / 72, rem = i % 72, ci = rem / 9, k = rem % 9;
            s_w[col][ci][k] = w[((size_t)(cog*4+col)*CC + c0+ci)*9 + k];
        }
        __syncthreads();
        #pragma unroll
        for (int ci = 0; ci < 8; ci++) {
            float v[9];
            #pragma unroll
            for (int j = 0; j < 9; j++) v[j] = s_in[ci][ty + j/3][tx + j%3];
            #pragma unroll
            for (int col = 0; col < 4; col++) {
                float a = acc[col];
                #pragma unroll
                for (int k = 0; k < 9; k++) a += v[k]*s_w[col][ci][k];
                acc[col] = a;
            }
        }
        __syncthreads();
    }
    int H2 = 2*H, W2 = 2*W;
    float* ob = out + ((size_t)bb*CC + cog)*H2*W2;
    int oy = y0 + ty, ox = x0 + tx;
    #pragma unroll
    for (int col = 0; col < 4; col++) {
        int r = col >> 1, s = col & 1;
        ob[(size_t)(2*oy + r)*W2 + 2*ox + s] = acc[col] + bias[cog*4 + col];
    }
}

__global__ void down_fused(const float* __restrict__ in3, const float* __restrict__ skin,
                           float* __restrict__ out, int OH, int OW,
                           const float* __restrict__ dw, const float* __restrict__ db,
                           const float* __restrict__ sw, const float* __restrict__ sb)
{
    __shared__ float s_in[8][33][33];
    __shared__ float s_w[4][8][9];
    __shared__ float s_sw[4][8];
    int IH = 2*OH, IW = 2*OW;
    int tx = threadIdx.x, ty = threadIdx.y, tid = ty*16 + tx;
    int x0 = blockIdx.x*16, y0 = blockIdx.y*16;
    int bb = blockIdx.z >> 4;
    int cog = blockIdx.z & 15;
    float acc[4] = {0.f,0.f,0.f,0.f};
    const float* inb = in3 + (size_t)bb*CC*IH*IW;
    const float* skb = skin + (size_t)bb*CC*OH*OW;
    int oy = y0 + ty, ox = x0 + tx;

    for (int c0 = 0; c0 < CC; c0 += 8) {
        for (int i = tid; i < 8*33*33; i += 256) {
            int ci = i / 1089, rem = i % 1089, r = rem / 33, c = rem % 33;
            int y = 2*y0 - 1 + r, x = 2*x0 - 1 + c;
            float v = 0.f;
            if (y >= 0 && y < IH && x >= 0 && x < IW)
                v = inb[(size_t)(c0+ci)*IH*IW + y*IW + x];
            s_in[ci][r][c] = v;
        }
        for (int i = tid; i < 288; i += 256) {
            int col = i / 72, rem = i % 72, ci = rem / 9, k = rem % 9;
            s_w[col][ci][k] = dw[((size_t)(cog*4+col)*CC + c0+ci)*9 + k];
        }
        if (tid < 32) {
            int col = tid >> 3, ci = tid & 7;
            s_sw[col][ci] = sw[(cog*4+col)*CC + c0+ci];
        }
        __syncthreads();
        #pragma unroll
        for (int ci = 0; ci < 8; ci++) {
            float v[9];
            #pragma unroll
            for (int j = 0; j < 9; j++) v[j] = s_in[ci][2*ty + j/3][2*tx + j%3];
            float sv = skb[(size_t)(c0+ci)*OH*OW + oy*OW + ox];
            #pragma unroll
            for (int col = 0; col < 4; col++) {
                float a = acc[col];
                #pragma unroll
                for (int k = 0; k < 9; k++) a += v[k]*s_w[col][ci][k];
                a += sv * s_sw[col][ci];
                acc[col] = a;
            }
        }
        __syncthreads();
    }
    float* ob = out + (size_t)bb*CC*OH*OW;
    #pragma unroll
    for (int col = 0; col < 4; col++) {
        int co = cog*4 + col;
        ob[(size_t)co*OH*OW + oy*OW + ox] = acc[col] + db[co] + sb[co];
    }
}

// ================= weight prep: transpose (fp32) =================
// layout: L0 at 0 (256 x 272), L1/L2/L3 at 69632 + l*65536 (256 x 256); row n, col k
__global__ void prep_wt(const float* __restrict__ w0, const float* __restrict__ w1,
                        const float* __restrict__ w2, const float* __restrict__ w3)
{
    int i = blockIdx.x*256 + threadIdx.x;
    int total = 256*K0P + 3*256*256;
    if (i >= total) return;
    float v;
    if (i < 256*K0P) {
        int n = i / K0P, k = i % K0P;
        v = (k < 260) ? w0[(size_t)k*256 + n] : 0.0f;
    } else {
        int j = i - 256*K0P;
        int l = j / 65536, r = j % 65536;
        int n = r / 256, k = r % 256;
        const float* ws = (l == 0) ? w1 : (l == 1) ? w2 : w3;
        v = ws[(size_t)k*256 + n];
    }
    g_Wt[i] = v;
}

// ================= gather + build X (fp32, K0P cols) =================
__device__ __forceinline__ int nidx(float cc, float n)
{
    float f = rintf((cc + 1.0f)*(n*0.5f) - 0.5f);
    f = fminf(fmaxf(f, 0.0f), n - 1.0f);
    return (int)f;
}

__global__ void gather_build(const float* __restrict__ coord, const float* __restrict__ cell)
{
    int tid = threadIdx.x;
    int row = blockIdx.x*4 + (tid >> 6);
    int c   = tid & 63;
    int s   = row & 3;
    int bq  = row >> 2;
    int b   = bq >> 14;
    float cy = coord[(size_t)bq*2 + 0];
    float cx = coord[(size_t)bq*2 + 1];
    float vx = (s & 2) ? 1.f : -1.f;
    float vy = (s & 1) ? 1.f : -1.f;
    const float RX = 1.0f/48.0f;
    float sy = fminf(fmaxf(cy + vx*RX + 1e-6f, -1.f + 1e-6f), 1.f - 1e-6f);
    float sx = fminf(fmaxf(cx + vy*RX + 1e-6f, -1.f + 1e-6f), 1.f - 1e-6f);
    int iy0 = nidx(sy, 48.f),  ix0 = nidx(sx, 48.f);
    int iy1 = nidx(sy, 96.f),  ix1 = nidx(sx, 96.f);
    int iy2 = nidx(sy, 192.f), ix2 = nidx(sx, 192.f);
    int iy3 = nidx(sy, 384.f), ix3 = nidx(sx, 384.f);

    float* xr = g_X + (size_t)row*K0P;
    xr[c]       = g_feat [((size_t)(b*CC + c)*48  + iy0)*48  + ix0];
    xr[64 + c]  = g_feat5[((size_t)(b*CC + c)*96  + iy1)*96  + ix1];
    xr[128 + c] = g_feat4[((size_t)(b*CC + c)*192 + iy2)*192 + ix2];
    xr[192 + c] = g_feat3[((size_t)(b*CC + c)*384 + iy3)*384 + ix3];
    if (c == 0) {
        float qcy = -1.f + (2.f*iy0 + 1.f)/48.f;
        float qcx = -1.f + (2.f*ix0 + 1.f)/48.f;
        float ry_ = (cy - qcy)*48.f;
        float rx_ = (cx - qcx)*48.f;
        xr[256] = ry_;
        xr[257] = rx_;
        xr[258] = cell[(size_t)bq*2 + 0]*48.f;
        xr[259] = cell[(size_t)bq*2 + 1]*48.f;
        g_area[row] = fabsf(ry_*rx_) + 1e-9f;
    }
    if (c < 12) xr[260 + c] = 0.0f;   // pad to 272
}

// ================= packed-f32x2 GEMM =================
// C[M,256] = relu(A[M,K] @ W + bias), W provided transposed Wt[n][k].
// Tile: BM=128, BN=64, BK=16; 128 threads; per-thread 8m (4 packed pairs) x 8n.
// Packed FMA: fma.rn.f32x2 (Blackwell base ISA) -> 2 fp32 MACs per instruction.
__global__ void __launch_bounds__(128)
gemm_f32x2(const float* __restrict__ A, const float* __restrict__ Wt,
           const float* __restrict__ bias, float* __restrict__ C,
           int K)
{
    __shared__ float As[16][128];                  // [k][m]
    __shared__ unsigned long long Bs[16][64];      // [k][n] duplicated pairs (b,b)
    int tid = threadIdx.x;
    int m0 = blockIdx.y*128, n0 = blockIdx.x*64;
    int msub = (tid >> 3)*8;          // 16 groups * 8 m
    int nsub = (tid & 7)*8;           // 8 groups * 8 n

    unsigned long long acc[4][8];
    #pragma unroll
    for (int mp = 0; mp < 4; mp++)
        #pragma unroll
        for (int j = 0; j < 8; j++) acc[mp][j] = 0ull;

    // loader indices
    int brow = tid >> 1;              // 0..63  (B row n)
    int bkh  = (tid & 1)*8;           // k half

    for (int k0 = 0; k0 < K; k0 += 16) {
        // ---- load A tile 128x16: one row per thread ----
        {
            const float* ap = A + (size_t)(m0 + tid)*K + k0;
            float4 v0 = *(const float4*)(ap + 0);
            float4 v1 = *(const float4*)(ap + 4);
            float4 v2 = *(const float4*)(ap + 8);
            float4 v3 = *(const float4*)(ap + 12);
            As[ 0][tid] = v0.x; As[ 1][tid] = v0.y; As[ 2][tid] = v0.z; As[ 3][tid] = v0.w;
            As[ 4][tid] = v1.x; As[ 5][tid] = v1.y; As[ 6][tid] = v1.z; As[ 7][tid] = v1.w;
            As[ 8][tid] = v2.x; As[ 9][tid] = v2.y; As[10][tid] = v2.z; As[11][tid] = v2.w;
            As[12][tid] = v3.x; As[13][tid] = v3.y; As[14][tid] = v3.z; As[15][tid] = v3.w;
        }
        // ---- load B tile 64x16 (Wt rows), duplicate into pairs ----
        {
            const float* bp = Wt + (size_t)(n0 + brow)*K + k0 + bkh;
            float4 v0 = *(const float4*)(bp + 0);
            float4 v1 = *(const float4*)(bp + 4);
            float bv[8] = {v0.x, v0.y, v0.z, v0.w, v1.x, v1.y, v1.z, v1.w};
            #pragma unroll
            for (int u = 0; u < 8; u++) {
                unsigned long long d;
                uint32_t r = __float_as_uint(bv[u]);
                asm("mov.b64 %0, {%1, %1};" : "=l"(d) : "r"(r));
                Bs[bkh + u][brow] = d;
            }
        }
        __syncthreads();

        #pragma unroll
        for (int kk = 0; kk < 16; kk++) {
            unsigned long long a2[4], b2[8];
            const unsigned long long* ap = (const unsigned long long*)&As[kk][msub];
            a2[0] = ap[0]; a2[1] = ap[1]; a2[2] = ap[2]; a2[3] = ap[3];
            #pragma unroll
            for (int j = 0; j < 8; j++) b2[j] = Bs[kk][nsub + j];
            #pragma unroll
            for (int mp = 0; mp < 4; mp++)
                #pragma unroll
                for (int j = 0; j < 8; j++)
                    asm("fma.rn.f32x2 %0, %1, %2, %0;"
                        : "+l"(acc[mp][j]) : "l"(a2[mp]), "l"(b2[j]));
        }
        __syncthreads();
    }

    // ---- epilogue: bias + relu ----
    float bb[8];
    #pragma unroll
    for (int j = 0; j < 8; j++) bb[j] = bias[n0 + nsub + j];
    #pragma unroll
    for (int mp = 0; mp < 4; mp++) {
        float r0[8], r1[8];
        #pragma unroll
        for (int j = 0; j < 8; j++) {
            uint32_t lo, hi;
            asm("mov.b64 {%0, %1}, %2;" : "=r"(lo), "=r"(hi) : "l"(acc[mp][j]));
            r0[j] = fmaxf(__uint_as_float(lo) + bb[j], 0.f);
            r1[j] = fmaxf(__uint_as_float(hi) + bb[j], 0.f);
        }
        int m = m0 + msub + 2*mp;
        float* c0 = C + (size_t)m*HID + n0 + nsub;
        float* c1 = c0 + HID;
        *(float4*)(c0)     = make_float4(r0[0], r0[1], r0[2], r0[3]);
        *(float4*)(c0 + 4) = make_float4(r0[4], r0[5], r0[6], r0[7]);
        *(float4*)(c1)     = make_float4(r1[0], r1[1], r1[2], r1[3]);
        *(float4*)(c1 + 4) = make_float4(r1[4], r1[5], r1[6], r1[7]);
    }
}

// ================= last layer: [M,256]@[256,3]+b =================
__global__ void mlp_last(const float* __restrict__ Hin, const float* __restrict__ W4,
                         const float* __restrict__ b4)
{
    int warp = threadIdx.x >> 5, lane = threadIdx.x & 31;
    int row = blockIdx.x*4 + warp;
    const float* hr = Hin + (size_t)row*HID;
    float a0 = 0.f, a1 = 0.f, a2 = 0.f;
    for (int k = lane; k < HID; k += 32) {
        float h = hr[k];
        a0 += h*W4[k*3 + 0];
        a1 += h*W4[k*3 + 1];
        a2 += h*W4[k*3 + 2];
    }
    #pragma unroll
    for (int o = 16; o; o >>= 1) {
        a0 += __shfl_down_sync(0xffffffffu, a0, o);
        a1 += __shfl_down_sync(0xffffffffu, a1, o);
        a2 += __shfl_down_sync(0xffffffffu, a2, o);
    }
    if (lane == 0) {
        g_P[(size_t)row*3 + 0] = a0 + b4[0];
        g_P[(size_t)row*3 + 1] = a1 + b4[1];
        g_P[(size_t)row*3 + 2] = a2 + b4[2];
    }
}

// ================= ensemble + bilinear border skip =================
__global__ void ensemble(const float* __restrict__ coord, const float* __restrict__ inp,
                         float* __restrict__ out)
{
    int bq = blockIdx.x*256 + threadIdx.x;
    if (bq >= BB*QQ) return;
    int b = bq >> 14;
    float cy = coord[(size_t)bq*2 + 0];
    float cx = coord[(size_t)bq*2 + 1];
    int base = bq*4;
    float a0 = g_area[base+0], a1 = g_area[base+1], a2 = g_area[base+2], a3 = g_area[base+3];
    float inv = 1.0f/(a0 + a1 + a2 + a3);
    float w0 = a3*inv, w1 = a2*inv, w2 = a1*inv, w3 = a0*inv;
    float r[3];
    #pragma unroll
    for (int c = 0; c < 3; c++) {
        r[c] = g_P[(size_t)(base+0)*3 + c]*w0
             + g_P[(size_t)(base+1)*3 + c]*w1
             + g_P[(size_t)(base+2)*3 + c]*w2
             + g_P[(size_t)(base+3)*3 + c]*w3;
    }
    float fy = fminf(fmaxf((cy + 1.f)*24.f - 0.5f, 0.f), 47.f);
    float fx = fminf(fmaxf((cx + 1.f)*24.f - 0.5f, 0.f), 47.f);
    float y0f = floorf(fy), x0f = floorf(fx);
    int y0 = (int)y0f, x0 = (int)x0f;
    float wy = fy - y0f, wx = fx - x0f;
    int y1 = min(y0 + 1, 47), x1 = min(x0 + 1, 47);
    const float* ib = inp + (size_t)b*3*H0*W0;
    #pragma unroll
    for (int ch = 0; ch < 3; ch++) {
        const float* p = ib + ch*H0*W0;
        float v00 = p[y0*48 + x0], v01 = p[y0*48 + x1];
        float v10 = p[y1*48 + x0], v11 = p[y1*48 + x1];
        r[ch] += v00*(1.f - wy)*(1.f - wx) + v01*(1.f - wy)*wx
               + v10*wy*(1.f - wx) + v11*wy*wx;
        out[(size_t)bq*3 + ch] = r[ch];
    }
}

// ================= host launch =================
extern "C" void kernel_launch(void* const* d_in, const int* in_sizes, int n_in,
                              void* d_out, int out_size)
{
    const float* inp     = (const float*)d_in[0];
    const float* coord   = (const float*)d_in[1];
    const float* cell    = (const float*)d_in[2];
    const float* enc_w   = (const float*)d_in[3];
    const float* enc_b   = (const float*)d_in[4];
    const float* up1_w   = (const float*)d_in[5];
    const float* up1_b   = (const float*)d_in[6];
    const float* up2_w   = (const float*)d_in[7];
    const float* up2_b   = (const float*)d_in[8];
    const float* up3_w   = (const float*)d_in[9];
    const float* up3_b   = (const float*)d_in[10];
    const float* skip1_w = (const float*)d_in[11];
    const float* skip1_b = (const float*)d_in[12];
    const float* skip2_w = (const float*)d_in[13];
    const float* skip2_b = (const float*)d_in[14];
    const float* down4_w = (const float*)d_in[15];
    const float* down4_b = (const float*)d_in[16];
    const float* down5_w = (const float*)d_in[17];
    const float* down5_b = (const float*)d_in[18];
    const float* mlp_w0  = (const float*)d_in[19];
    const float* mlp_b0  = (const float*)d_in[20];
    const float* mlp_w1  = (const float*)d_in[21];
    const float* mlp_b1  = (const float*)d_in[22];
    const float* mlp_w2  = (const float*)d_in[23];
    const float* mlp_b2  = (const float*)d_in[24];
    const float* mlp_w3  = (const float*)d_in[25];
    const float* mlp_b3  = (const float*)d_in[26];
    const float* mlp_w4  = (const float*)d_in[27];
    const float* mlp_b4  = (const float*)d_in[28];
    float* out = (float*)d_out;

    float *p_feat, *p_feat1, *p_feat2, *p_feat3, *p_feat4, *p_feat5;
    float *p_X, *p_H0, *p_H1, *p_Wt;
    cudaGetSymbolAddress((void**)&p_feat,  g_feat);
    cudaGetSymbolAddress((void**)&p_feat1, g_feat1);
    cudaGetSymbolAddress((void**)&p_feat2, g_feat2);
    cudaGetSymbolAddress((void**)&p_feat3, g_feat3);
    cudaGetSymbolAddress((void**)&p_feat4, g_feat4);
    cudaGetSymbolAddress((void**)&p_feat5, g_feat5);
    cudaGetSymbolAddress((void**)&p_X,  g_X);
    cudaGetSymbolAddress((void**)&p_H0, g_H0b);
    cudaGetSymbolAddress((void**)&p_H1, g_H1b);
    cudaGetSymbolAddress((void**)&p_Wt, g_Wt);

    // weight prep (independent of convs)
    {
        int total = 256*K0P + 3*256*256;
        prep_wt<<<(total + 255)/256, 256>>>(mlp_w0, mlp_w1, mlp_w2, mlp_w3);
    }
    // encoder + pyramid
    {
        int total = BB*CC*H0*W0;
        enc_conv<<<(total + 255)/256, 256>>>(inp, enc_w, enc_b);
        dim3 blk(16,16);
        up_conv_ps<<<dim3(3,  3,  BB*64), blk>>>(p_feat,  p_feat1, 48, 48,  up1_w, up1_b);
        up_conv_ps<<<dim3(6,  6,  BB*64), blk>>>(p_feat1, p_feat2, 96, 96,  up2_w, up2_b);
        up_conv_ps<<<dim3(12, 12, BB*64), blk>>>(p_feat2, p_feat3, 192,192, up3_w, up3_b);
        down_fused<<<dim3(12, 12, BB*16), blk>>>(p_feat3, p_feat2, p_feat4, 192, 192,
                                                 down4_w, down4_b, skip1_w, skip1_b);
        down_fused<<<dim3(6,  6,  BB*16), blk>>>(p_feat4, p_feat1, p_feat5, 96, 96,
                                                 down5_w, down5_b, skip2_w, skip2_b);
    }
    // gather + build X (fp32, padded to 272)
    gather_build<<<MROWS/4, 256>>>(coord, cell);

    // MLP hidden layers on packed-f32x2 pipe
    {
        dim3 grid(HID/64, MROWS/128);   // (4, 2048)
        const float* W1 = p_Wt + 256*K0P;
        const float* W2 = W1 + 65536;
        const float* W3 = W2 + 65536;
        gemm_f32x2<<<grid, 128>>>(p_X,  p_Wt, mlp_b0, p_H0, K0P);
        gemm_f32x2<<<grid, 128>>>(p_H0, W1,   mlp_b1, p_H1, 256);
        gemm_f32x2<<<grid, 128>>>(p_H1, W2,   mlp_b2, p_H0, 256);
        gemm_f32x2<<<grid, 128>>>(p_H0, W3,   mlp_b3, p_H1, 256);
    }
    // last layer + ensemble
    mlp_last<<<MROWS/4, 128>>>(p_H1, mlp_w4, mlp_b4);
    ensemble<<<(BB*QQ + 255)/256, 256>>>(coord, inp, out);
}

// round 7
// speedup vs baseline: 1.8458x; 1.8458x over previous
#include <cuda_runtime.h>
#include <cuda_bf16.h>
#include <cstdint>

// ---------------- problem constants ----------------
#define BB     4
#define CC     64
#define H0     48
#define W0     48
#define QQ     16384
#define MROWS  (BB*QQ*4)     // 262144
#define HID    256
#define K0P    272           // layer-0 K (260) padded to multiple of 8

// ---------------- scratch ----------------
__device__ float g_feat [BB*CC*H0*W0];
__device__ float g_feat1[BB*CC*96*96];
__device__ float g_feat2[BB*CC*192*192];
__device__ float g_feat3[BB*CC*384*384];
__device__ float g_feat4[BB*CC*192*192];
__device__ float g_feat5[BB*CC*96*96];
__device__ float g_X  [(size_t)MROWS*K0P];
__device__ float g_H0b[(size_t)MROWS*HID];
__device__ float g_H1b[(size_t)MROWS*HID];
__device__ float g_Wt [256*K0P + 3*256*256];   // transposed weights [n][k]
__device__ float g_P  [(size_t)MROWS*3];
__device__ float g_area[MROWS];

// ================= enc conv (tiny, unchanged) =================
__global__ void enc_conv(const float* __restrict__ inp,
                         const float* __restrict__ w,
                         const float* __restrict__ b)
{
    int idx = blockIdx.x*256 + threadIdx.x;
    if (idx >= BB*CC*H0*W0) return;
    int x  = idx % W0;
    int y  = (idx / W0) % H0;
    int co = (idx / (H0*W0)) % CC;
    int bb = idx / (H0*W0*CC);
    float acc = b[co];
    const float* ib = inp + (size_t)bb*3*H0*W0;
    #pragma unroll
    for (int ci = 0; ci < 3; ci++) {
        #pragma unroll
        for (int ky = 0; ky < 3; ky++) {
            int yy = y + ky - 1;
            if (yy < 0 || yy >= H0) continue;
            #pragma unroll
            for (int kx = 0; kx < 3; kx++) {
                int xx = x + kx - 1;
                if (xx < 0 || xx >= W0) continue;
                acc += ib[ci*H0*W0 + yy*W0 + xx] * w[(co*3 + ci)*9 + ky*3 + kx];
            }
        }
    }
    g_feat[idx] = acc;
}

// ================= up conv 3x3 (64->256) + pixel shuffle, 2x4 px/thread =================
// grid (ceil(W/32), ceil(H/32), B*64), block 128 (tx=tid&7 -> x*4, ty=tid>>3 -> y*2)
__global__ void __launch_bounds__(128)
up_conv_ps2(const float* __restrict__ in, float* __restrict__ out,
            int H, int W,
            const float* __restrict__ w, const float* __restrict__ bias)
{
    __shared__ float s_in[4][34][34];
    int tid = threadIdx.x;
    int tx = tid & 7, ty = tid >> 3;
    int x0 = blockIdx.x*32, y0 = blockIdx.y*32;
    int bb = blockIdx.z >> 6;
    int cog = blockIdx.z & 63;
    const float* inb = in + (size_t)bb*CC*H*W;
    int bxp = x0 + tx*4;        // base output-x of this thread (4 px)
    int byp = y0 + ty*2;        // base output-y (2 px)

    float acc[4][8];
    #pragma unroll
    for (int c = 0; c < 4; c++)
        #pragma unroll
        for (int p = 0; p < 8; p++) acc[c][p] = 0.f;

    for (int c0 = 0; c0 < CC; c0 += 4) {
        for (int i = tid; i < 4*34*34; i += 128) {
            int ci = i / 1156, rem = i % 1156, r = rem / 34, c = rem % 34;
            int y = y0 + r - 1, x = x0 + c - 1;
            float v = 0.f;
            if (y >= 0 && y < H && x >= 0 && x < W)
                v = inb[(size_t)(c0+ci)*H*W + y*W + x];
            s_in[ci][r][c] = v;
        }
        __syncthreads();
        #pragma unroll
        for (int ci = 0; ci < 4; ci++) {
            float wr[4][9];
            #pragma unroll
            for (int col = 0; col < 4; col++) {
                const float* wp = w + ((size_t)(cog*4+col)*CC + c0+ci)*9;
                #pragma unroll
                for (int k = 0; k < 9; k++) wr[col][k] = __ldg(wp + k);
            }
            float v[4][6];
            #pragma unroll
            for (int r = 0; r < 4; r++)
                #pragma unroll
                for (int c = 0; c < 6; c++)
                    v[r][c] = s_in[ci][ty*2 + r][tx*4 + c];
            #pragma unroll
            for (int col = 0; col < 4; col++)
                #pragma unroll
                for (int py = 0; py < 2; py++)
                    #pragma unroll
                    for (int px = 0; px < 4; px++) {
                        float a = acc[col][py*4 + px];
                        #pragma unroll
                        for (int ky = 0; ky < 3; ky++)
                            #pragma unroll
                            for (int kx = 0; kx < 3; kx++)
                                a += v[py+ky][px+kx] * wr[col][ky*3+kx];
                        acc[col][py*4 + px] = a;
                    }
        }
        __syncthreads();
    }

    if (bxp < W) {
        float b4[4];
        #pragma unroll
        for (int c = 0; c < 4; c++) b4[c] = bias[cog*4 + c];
        int H2 = 2*H, W2 = 2*W;
        float* ob = out + ((size_t)bb*CC + cog)*H2*W2;
        #pragma unroll
        for (int py = 0; py < 2; py++) {
            int yo = byp + py;
            if (yo >= H) continue;
            #pragma unroll
            for (int r = 0; r < 2; r++) {
                float* orow = ob + (size_t)(2*yo + r)*W2 + 2*bxp;
                float4 q0 = make_float4(acc[2*r+0][py*4+0] + b4[2*r+0],
                                        acc[2*r+1][py*4+0] + b4[2*r+1],
                                        acc[2*r+0][py*4+1] + b4[2*r+0],
                                        acc[2*r+1][py*4+1] + b4[2*r+1]);
                float4 q1 = make_float4(acc[2*r+0][py*4+2] + b4[2*r+0],
                                        acc[2*r+1][py*4+2] + b4[2*r+1],
                                        acc[2*r+0][py*4+3] + b4[2*r+0],
                                        acc[2*r+1][py*4+3] + b4[2*r+1]);
                *(float4*)(orow)     = q0;
                *(float4*)(orow + 4) = q1;
            }
        }
    }
}

// ================= stride2 conv3x3 + 1x1 skip (unchanged, passing) =================
__global__ void down_fused(const float* __restrict__ in3, const float* __restrict__ skin,
                           float* __restrict__ out, int OH, int OW,
                           const float* __restrict__ dw, const float* __restrict__ db,
                           const float* __restrict__ sw, const float* __restrict__ sb)
{
    __shared__ float s_in[8][33][33];
    __shared__ float s_w[4][8][9];
    __shared__ float s_sw[4][8];
    int IH = 2*OH, IW = 2*OW;
    int tx = threadIdx.x, ty = threadIdx.y, tid = ty*16 + tx;
    int x0 = blockIdx.x*16, y0 = blockIdx.y*16;
    int bb = blockIdx.z >> 4;
    int cog = blockIdx.z & 15;
    float acc[4] = {0.f,0.f,0.f,0.f};
    const float* inb = in3 + (size_t)bb*CC*IH*IW;
    const float* skb = skin + (size_t)bb*CC*OH*OW;
    int oy = y0 + ty, ox = x0 + tx;

    for (int c0 = 0; c0 < CC; c0 += 8) {
        for (int i = tid; i < 8*33*33; i += 256) {
            int ci = i / 1089, rem = i % 1089, r = rem / 33, c = rem % 33;
            int y = 2*y0 - 1 + r, x = 2*x0 - 1 + c;
            float v = 0.f;
            if (y >= 0 && y < IH && x >= 0 && x < IW)
                v = inb[(size_t)(c0+ci)*IH*IW + y*IW + x];
            s_in[ci][r][c] = v;
        }
        for (int i = tid; i < 288; i += 256) {
            int col = i / 72, rem = i % 72, ci = rem / 9, k = rem % 9;
            s_w[col][ci][k] = dw[((size_t)(cog*4+col)*CC + c0+ci)*9 + k];
        }
        if (tid < 32) {
            int col = tid >> 3, ci = tid & 7;
            s_sw[col][ci] = sw[(cog*4+col)*CC + c0+ci];
        }
        __syncthreads();
        #pragma unroll
        for (int ci = 0; ci < 8; ci++) {
            float v[9];
            #pragma unroll
            for (int j = 0; j < 9; j++) v[j] = s_in[ci][2*ty + j/3][2*tx + j%3];
            float sv = skb[(size_t)(c0+ci)*OH*OW + oy*OW + ox];
            #pragma unroll
            for (int col = 0; col < 4; col++) {
                float a = acc[col];
                #pragma unroll
                for (int k = 0; k < 9; k++) a += v[k]*s_w[col][ci][k];
                a += sv * s_sw[col][ci];
                acc[col] = a;
            }
        }
        __syncthreads();
    }
    float* ob = out + (size_t)bb*CC*OH*OW;
    #pragma unroll
    for (int col = 0; col < 4; col++) {
        int co = cog*4 + col;
        ob[(size_t)co*OH*OW + oy*OW + ox] = acc[col] + db[co] + sb[co];
    }
}

// ================= weight prep: transpose (fp32) =================
__global__ void prep_wt(const float* __restrict__ w0, const float* __restrict__ w1,
                        const float* __restrict__ w2, const float* __restrict__ w3)
{
    int i = blockIdx.x*256 + threadIdx.x;
    int total = 256*K0P + 3*256*256;
    if (i >= total) return;
    float v;
    if (i < 256*K0P) {
        int n = i / K0P, k = i % K0P;
        v = (k < 260) ? w0[(size_t)k*256 + n] : 0.0f;
    } else {
        int j = i - 256*K0P;
        int l = j / 65536, r = j % 65536;
        int n = r / 256, k = r % 256;
        const float* ws = (l == 0) ? w1 : (l == 1) ? w2 : w3;
        v = ws[(size_t)k*256 + n];
    }
    g_Wt[i] = v;
}

// ================= gather + build X =================
__device__ __forceinline__ int nidx(float cc, float n)
{
    float f = rintf((cc + 1.0f)*(n*0.5f) - 0.5f);
    f = fminf(fmaxf(f, 0.0f), n - 1.0f);
    return (int)f;
}

__global__ void gather_build(const float* __restrict__ coord, const float* __restrict__ cell)
{
    int tid = threadIdx.x;
    int row = blockIdx.x*4 + (tid >> 6);
    int c   = tid & 63;
    int s   = row & 3;
    int bq  = row >> 2;
    int b   = bq >> 14;
    float cy = coord[(size_t)bq*2 + 0];
    float cx = coord[(size_t)bq*2 + 1];
    float vx = (s & 2) ? 1.f : -1.f;
    float vy = (s & 1) ? 1.f : -1.f;
    const float RX = 1.0f/48.0f;
    float sy = fminf(fmaxf(cy + vx*RX + 1e-6f, -1.f + 1e-6f), 1.f - 1e-6f);
    float sx = fminf(fmaxf(cx + vy*RX + 1e-6f, -1.f + 1e-6f), 1.f - 1e-6f);
    int iy0 = nidx(sy, 48.f),  ix0 = nidx(sx, 48.f);
    int iy1 = nidx(sy, 96.f),  ix1 = nidx(sx, 96.f);
    int iy2 = nidx(sy, 192.f), ix2 = nidx(sx, 192.f);
    int iy3 = nidx(sy, 384.f), ix3 = nidx(sx, 384.f);

    float* xr = g_X + (size_t)row*K0P;
    xr[c]       = g_feat [((size_t)(b*CC + c)*48  + iy0)*48  + ix0];
    xr[64 + c]  = g_feat5[((size_t)(b*CC + c)*96  + iy1)*96  + ix1];
    xr[128 + c] = g_feat4[((size_t)(b*CC + c)*192 + iy2)*192 + ix2];
    xr[192 + c] = g_feat3[((size_t)(b*CC + c)*384 + iy3)*384 + ix3];
    if (c == 0) {
        float qcy = -1.f + (2.f*iy0 + 1.f)/48.f;
        float qcx = -1.f + (2.f*ix0 + 1.f)/48.f;
        float ry_ = (cy - qcy)*48.f;
        float rx_ = (cx - qcx)*48.f;
        xr[256] = ry_;
        xr[257] = rx_;
        xr[258] = cell[(size_t)bq*2 + 0]*48.f;
        xr[259] = cell[(size_t)bq*2 + 1]*48.f;
        g_area[row] = fabsf(ry_*rx_) + 1e-9f;
    }
    if (c < 12) xr[260 + c] = 0.0f;   // pad to 272
}

// ================= scalar-FFMA SGEMM, 128x128 tile, 8x8/thread =================
// C[M,256] = relu(A[M,K] @ W + bias), W transposed Wt[n][k].
// 256 threads; split register tiles for conflict-free LDS.128; 1 sync/K-block.
__global__ void __launch_bounds__(256)
gemm_f32(const float* __restrict__ A, const float* __restrict__ Wt,
         const float* __restrict__ bias, float* __restrict__ C, int K)
{
    __shared__ float As[2][8][128];
    __shared__ float Bs[2][8][128];
    int tid = threadIdx.x;
    int tx = tid & 15, ty = tid >> 4;
    int m0 = blockIdx.y*128, n0 = blockIdx.x*128;
    int lrow = tid >> 1, lk = (tid & 1)*4;
    const float* ap = A  + (size_t)(m0 + lrow)*K + lk;
    const float* bp = Wt + (size_t)(n0 + lrow)*K + lk;
    int NK = K >> 3;

    float acc[8][8];
    #pragma unroll
    for (int i = 0; i < 8; i++)
        #pragma unroll
        for (int j = 0; j < 8; j++) acc[i][j] = 0.f;

    float4 av = *(const float4*)ap;
    float4 bv = *(const float4*)bp;

    for (int it = 0; it < NK; it++) {
        int buf = it & 1;
        As[buf][lk+0][lrow] = av.x;
        As[buf][lk+1][lrow] = av.y;
        As[buf][lk+2][lrow] = av.z;
        As[buf][lk+3][lrow] = av.w;
        Bs[buf][lk+0][lrow] = bv.x;
        Bs[buf][lk+1][lrow] = bv.y;
        Bs[buf][lk+2][lrow] = bv.z;
        Bs[buf][lk+3][lrow] = bv.w;
        if (it + 1 < NK) {
            av = *(const float4*)(ap + (it+1)*8);
            bv = *(const float4*)(bp + (it+1)*8);
        }
        __syncthreads();
        #pragma unroll
        for (int kk = 0; kk < 8; kk++) {
            float a[8], b[8];
            *(float4*)(a)   = *(const float4*)&As[buf][kk][ty*4];
            *(float4*)(a+4) = *(const float4*)&As[buf][kk][ty*4 + 64];
            *(float4*)(b)   = *(const float4*)&Bs[buf][kk][tx*4];
            *(float4*)(b+4) = *(const float4*)&Bs[buf][kk][tx*4 + 64];
            #pragma unroll
            for (int i = 0; i < 8; i++)
                #pragma unroll
                for (int j = 0; j < 8; j++)
                    acc[i][j] += a[i]*b[j];
        }
    }

    float bn[8];
    #pragma unroll
    for (int j = 0; j < 8; j++)
        bn[j] = bias[n0 + ((j < 4) ? tx*4 + j : 64 + tx*4 + j - 4)];
    #pragma unroll
    for (int i = 0; i < 8; i++) {
        int m = m0 + ((i < 4) ? ty*4 + i : 64 + ty*4 + i - 4);
        float* cr = C + (size_t)m*HID + n0;
        float4 q0 = make_float4(fmaxf(acc[i][0] + bn[0], 0.f),
                                fmaxf(acc[i][1] + bn[1], 0.f),
                                fmaxf(acc[i][2] + bn[2], 0.f),
                                fmaxf(acc[i][3] + bn[3], 0.f));
        float4 q1 = make_float4(fmaxf(acc[i][4] + bn[4], 0.f),
                                fmaxf(acc[i][5] + bn[5], 0.f),
                                fmaxf(acc[i][6] + bn[6], 0.f),
                                fmaxf(acc[i][7] + bn[7], 0.f));
        *(float4*)(cr + tx*4)      = q0;
        *(float4*)(cr + 64 + tx*4) = q1;
    }
}

// ================= last layer: [M,256]@[256,3]+b =================
__global__ void mlp_last(const float* __restrict__ Hin, const float* __restrict__ W4,
                         const float* __restrict__ b4)
{
    int warp = threadIdx.x >> 5, lane = threadIdx.x & 31;
    int row = blockIdx.x*4 + warp;
    const float* hr = Hin + (size_t)row*HID;
    float a0 = 0.f, a1 = 0.f, a2 = 0.f;
    for (int k = lane; k < HID; k += 32) {
        float h = hr[k];
        a0 += h*W4[k*3 + 0];
        a1 += h*W4[k*3 + 1];
        a2 += h*W4[k*3 + 2];
    }
    #pragma unroll
    for (int o = 16; o; o >>= 1) {
        a0 += __shfl_down_sync(0xffffffffu, a0, o);
        a1 += __shfl_down_sync(0xffffffffu, a1, o);
        a2 += __shfl_down_sync(0xffffffffu, a2, o);
    }
    if (lane == 0) {
        g_P[(size_t)row*3 + 0] = a0 + b4[0];
        g_P[(size_t)row*3 + 1] = a1 + b4[1];
        g_P[(size_t)row*3 + 2] = a2 + b4[2];
    }
}

// ================= ensemble + bilinear border skip =================
__global__ void ensemble(const float* __restrict__ coord, const float* __restrict__ inp,
                         float* __restrict__ out)
{
    int bq = blockIdx.x*256 + threadIdx.x;
    if (bq >= BB*QQ) return;
    int b = bq >> 14;
    float cy = coord[(size_t)bq*2 + 0];
    float cx = coord[(size_t)bq*2 + 1];
    int base = bq*4;
    float a0 = g_area[base+0], a1 = g_area[base+1], a2 = g_area[base+2], a3 = g_area[base+3];
    float inv = 1.0f/(a0 + a1 + a2 + a3);
    float w0 = a3*inv, w1 = a2*inv, w2 = a1*inv, w3 = a0*inv;
    float r[3];
    #pragma unroll
    for (int c = 0; c < 3; c++) {
        r[c] = g_P[(size_t)(base+0)*3 + c]*w0
             + g_P[(size_t)(base+1)*3 + c]*w1
             + g_P[(size_t)(base+2)*3 + c]*w2
             + g_P[(size_t)(base+3)*3 + c]*w3;
    }
    float fy = fminf(fmaxf((cy + 1.f)*24.f - 0.5f, 0.f), 47.f);
    float fx = fminf(fmaxf((cx + 1.f)*24.f - 0.5f, 0.f), 47.f);
    float y0f = floorf(fy), x0f = floorf(fx);
    int y0 = (int)y0f, x0 = (int)x0f;
    float wy = fy - y0f, wx = fx - x0f;
    int y1 = min(y0 + 1, 47), x1 = min(x0 + 1, 47);
    const float* ib = inp + (size_t)b*3*H0*W0;
    #pragma unroll
    for (int ch = 0; ch < 3; ch++) {
        const float* p = ib + ch*H0*W0;
        float v00 = p[y0*48 + x0], v01 = p[y0*48 + x1];
        float v10 = p[y1*48 + x0], v11 = p[y1*48 + x1];
        r[ch] += v00*(1.f - wy)*(1.f - wx) + v01*(1.f - wy)*wx
               + v10*wy*(1.f - wx) + v11*wy*wx;
        out[(size_t)bq*3 + ch] = r[ch];
    }
}

// ================= host launch =================
extern "C" void kernel_launch(void* const* d_in, const int* in_sizes, int n_in,
                              void* d_out, int out_size)
{
    const float* inp     = (const float*)d_in[0];
    const float* coord   = (const float*)d_in[1];
    const float* cell    = (const float*)d_in[2];
    const float* enc_w   = (const float*)d_in[3];
    const float* enc_b   = (const float*)d_in[4];
    const float* up1_w   = (const float*)d_in[5];
    const float* up1_b   = (const float*)d_in[6];
    const float* up2_w   = (const float*)d_in[7];
    const float* up2_b   = (const float*)d_in[8];
    const float* up3_w   = (const float*)d_in[9];
    const float* up3_b   = (const float*)d_in[10];
    const float* skip1_w = (const float*)d_in[11];
    const float* skip1_b = (const float*)d_in[12];
    const float* skip2_w = (const float*)d_in[13];
    const float* skip2_b = (const float*)d_in[14];
    const float* down4_w = (const float*)d_in[15];
    const float* down4_b = (const float*)d_in[16];
    const float* down5_w = (const float*)d_in[17];
    const float* down5_b = (const float*)d_in[18];
    const float* mlp_w0  = (const float*)d_in[19];
    const float* mlp_b0  = (const float*)d_in[20];
    const float* mlp_w1  = (const float*)d_in[21];
    const float* mlp_b1  = (const float*)d_in[22];
    const float* mlp_w2  = (const float*)d_in[23];
    const float* mlp_b2  = (const float*)d_in[24];
    const float* mlp_w3  = (const float*)d_in[25];
    const float* mlp_b3  = (const float*)d_in[26];
    const float* mlp_w4  = (const float*)d_in[27];
    const float* mlp_b4  = (const float*)d_in[28];
    float* out = (float*)d_out;

    float *p_feat, *p_feat1, *p_feat2, *p_feat3, *p_feat4, *p_feat5;
    float *p_X, *p_H0, *p_H1, *p_Wt;
    cudaGetSymbolAddress((void**)&p_feat,  g_feat);
    cudaGetSymbolAddress((void**)&p_feat1, g_feat1);
    cudaGetSymbolAddress((void**)&p_feat2, g_feat2);
    cudaGetSymbolAddress((void**)&p_feat3, g_feat3);
    cudaGetSymbolAddress((void**)&p_feat4, g_feat4);
    cudaGetSymbolAddress((void**)&p_feat5, g_feat5);
    cudaGetSymbolAddress((void**)&p_X,  g_X);
    cudaGetSymbolAddress((void**)&p_H0, g_H0b);
    cudaGetSymbolAddress((void**)&p_H1, g_H1b);
    cudaGetSymbolAddress((void**)&p_Wt, g_Wt);

    // weight prep (independent of convs)
    {
        int total = 256*K0P + 3*256*256;
        prep_wt<<<(total + 255)/256, 256>>>(mlp_w0, mlp_w1, mlp_w2, mlp_w3);
    }
    // encoder + pyramid
    {
        int total = BB*CC*H0*W0;
        enc_conv<<<(total + 255)/256, 256>>>(inp, enc_w, enc_b);
        up_conv_ps2<<<dim3(2, 2, BB*64), 128>>>(p_feat,  p_feat1, 48, 48,  up1_w, up1_b);
        up_conv_ps2<<<dim3(3, 3, BB*64), 128>>>(p_feat1, p_feat2, 96, 96,  up2_w, up2_b);
        up_conv_ps2<<<dim3(6, 6, BB*64), 128>>>(p_feat2, p_feat3, 192,192, up3_w, up3_b);
        dim3 blk(16,16);
        down_fused<<<dim3(12, 12, BB*16), blk>>>(p_feat3, p_feat2, p_feat4, 192, 192,
                                                 down4_w, down4_b, skip1_w, skip1_b);
        down_fused<<<dim3(6,  6,  BB*16), blk>>>(p_feat4, p_feat1, p_feat5, 96, 96,
                                                 down5_w, down5_b, skip2_w, skip2_b);
    }
    // gather + build X (fp32, padded to 272)
    gather_build<<<MROWS/4, 256>>>(coord, cell);

    // MLP hidden layers: scalar-FFMA 128x128 GEMM
    {
        dim3 grid(HID/128, MROWS/128);   // (2, 2048)
        const float* W1 = p_Wt + 256*K0P;
        const float* W2 = W1 + 65536;
        const float* W3 = W2 + 65536;
        gemm_f32<<<grid, 256>>>(p_X,  p_Wt, mlp_b0, p_H0, K0P);
        gemm_f32<<<grid, 256>>>(p_H0, W1,   mlp_b1, p_H1, 256);
        gemm_f32<<<grid, 256>>>(p_H1, W2,   mlp_b2, p_H0, 256);
        gemm_f32<<<grid, 256>>>(p_H0, W3,   mlp_b3, p_H1, 256);
    }
    // last layer + ensemble
    mlp_last<<<MROWS/4, 128>>>(p_H1, mlp_w4, mlp_b4);
    ensemble<<<(BB*QQ + 255)/256, 256>>>(coord, inp, out);
}

// round 8
// speedup vs baseline: 1.8689x; 1.0125x over previous
#include <cuda_runtime.h>
#include <cuda_bf16.h>
#include <cstdint>

// ---------------- problem constants ----------------
#define BB     4
#define CC     64
#define H0     48
#define W0     48
#define QQ     16384
#define MROWS  (BB*QQ*4)     // 262144
#define HID    256
#define K0P    272           // layer-0 K (260) padded to multiple of 8

// ---------------- scratch ----------------
__device__ float g_feat [BB*CC*H0*W0];
__device__ float g_feat1[BB*CC*96*96];
__device__ float g_feat2[BB*CC*192*192];
__device__ float g_feat3[BB*CC*384*384];
__device__ float g_feat4[BB*CC*192*192];
__device__ float g_feat5[BB*CC*96*96];
__device__ float g_X  [(size_t)MROWS*K0P];
__device__ float g_H0b[(size_t)MROWS*HID];
__device__ float g_H1b[(size_t)MROWS*HID];
__device__ float g_Wt [256*K0P + 3*256*256];   // transposed weights [n][k]
__device__ float g_P  [(size_t)MROWS*3];
__device__ float g_area[MROWS];

// ================= enc conv (tiny, unchanged) =================
__global__ void enc_conv(const float* __restrict__ inp,
                         const float* __restrict__ w,
                         const float* __restrict__ b)
{
    int idx = blockIdx.x*256 + threadIdx.x;
    if (idx >= BB*CC*H0*W0) return;
    int x  = idx % W0;
    int y  = (idx / W0) % H0;
    int co = (idx / (H0*W0)) % CC;
    int bb = idx / (H0*W0*CC);
    float acc = b[co];
    const float* ib = inp + (size_t)bb*3*H0*W0;
    #pragma unroll
    for (int ci = 0; ci < 3; ci++) {
        #pragma unroll
        for (int ky = 0; ky < 3; ky++) {
            int yy = y + ky - 1;
            if (yy < 0 || yy >= H0) continue;
            #pragma unroll
            for (int kx = 0; kx < 3; kx++) {
                int xx = x + kx - 1;
                if (xx < 0 || xx >= W0) continue;
                acc += ib[ci*H0*W0 + yy*W0 + xx] * w[(co*3 + ci)*9 + ky*3 + kx];
            }
        }
    }
    g_feat[idx] = acc;
}

// ================= up conv 3x3 (64->256) + pixel shuffle =================
// grid (ceil(W/32), ceil(H/32), B*64), block 128. 2x4 px/thread.
// All weights for this cog preloaded into smem once; vectorized LDS.128 paths.
__global__ void __launch_bounds__(128)
up_conv_ps3(const float* __restrict__ in, float* __restrict__ out,
            int H, int W,
            const float* __restrict__ w, const float* __restrict__ bias)
{
    __shared__ float s_w[64][4][12];      // [ci][col][9 padded to 12] -> 12.3 KB
    __shared__ float s_in[4][34][36];     // rows padded to 36 floats  -> 19.6 KB
    int tid = threadIdx.x;
    int tx = tid & 7, ty = tid >> 3;
    int x0 = blockIdx.x*32, y0 = blockIdx.y*32;
    int bb = blockIdx.z >> 6;
    int cog = blockIdx.z & 63;
    const float* inb = in + (size_t)bb*CC*H*W;
    int bxp = x0 + tx*4;
    int byp = y0 + ty*2;

    // one-time weight preload: s_w[ci][col][k] = w[((cog*4+col)*64+ci)*9+k]
    for (int i = tid; i < 64*36; i += 128) {
        int ci = i / 36, rem = i % 36;
        int col = rem / 9, k = rem % 9;
        s_w[ci][col][k] = w[((size_t)(cog*4 + col)*CC + ci)*9 + k];
    }

    float acc[4][8];
    #pragma unroll
    for (int c = 0; c < 4; c++)
        #pragma unroll
        for (int p = 0; p < 8; p++) acc[c][p] = 0.f;

    for (int c0 = 0; c0 < CC; c0 += 4) {
        __syncthreads();   // protect s_in reuse (and s_w preload on first iter)
        for (int i = tid; i < 4*1156; i += 128) {
            int ci = i / 1156, rem = i % 1156;
            int r = rem / 34, c = rem % 34;
            int y = y0 + r - 1, x = x0 + c - 1;
            float v = 0.f;
            if (y >= 0 && y < H && x >= 0 && x < W)
                v = inb[(size_t)(c0+ci)*H*W + y*W + x];
            s_in[ci][r][c] = v;
        }
        __syncthreads();
        #pragma unroll
        for (int ci = 0; ci < 4; ci++) {
            float v[4][8];
            #pragma unroll
            for (int r = 0; r < 4; r++) {
                float4 p0 = *(const float4*)&s_in[ci][ty*2 + r][tx*4];
                float4 p1 = *(const float4*)&s_in[ci][ty*2 + r][tx*4 + 4];
                v[r][0] = p0.x; v[r][1] = p0.y; v[r][2] = p0.z; v[r][3] = p0.w;
                v[r][4] = p1.x; v[r][5] = p1.y; v[r][6] = p1.z; v[r][7] = p1.w;
            }
            #pragma unroll
            for (int col = 0; col < 4; col++) {
                float4 w0 = *(const float4*)&s_w[c0+ci][col][0];
                float4 w1 = *(const float4*)&s_w[c0+ci][col][4];
                float4 w2 = *(const float4*)&s_w[c0+ci][col][8];
                float wr[9] = {w0.x, w0.y, w0.z, w0.w, w1.x, w1.y, w1.z, w1.w, w2.x};
                #pragma unroll
                for (int py = 0; py < 2; py++)
                    #pragma unroll
                    for (int px = 0; px < 4; px++) {
                        float a = acc[col][py*4 + px];
                        #pragma unroll
                        for (int ky = 0; ky < 3; ky++)
                            #pragma unroll
                            for (int kx = 0; kx < 3; kx++)
                                a += v[py+ky][px+kx] * wr[ky*3+kx];
                        acc[col][py*4 + px] = a;
                    }
            }
        }
    }

    if (bxp < W) {
        float b4[4];
        #pragma unroll
        for (int c = 0; c < 4; c++) b4[c] = bias[cog*4 + c];
        int H2 = 2*H, W2 = 2*W;
        float* ob = out + ((size_t)bb*CC + cog)*H2*W2;
        #pragma unroll
        for (int py = 0; py < 2; py++) {
            int yo = byp + py;
            if (yo >= H) continue;
            #pragma unroll
            for (int r = 0; r < 2; r++) {
                float* orow = ob + (size_t)(2*yo + r)*W2 + 2*bxp;
                float4 q0 = make_float4(acc[2*r+0][py*4+0] + b4[2*r+0],
                                        acc[2*r+1][py*4+0] + b4[2*r+1],
                                        acc[2*r+0][py*4+1] + b4[2*r+0],
                                        acc[2*r+1][py*4+1] + b4[2*r+1]);
                float4 q1 = make_float4(acc[2*r+0][py*4+2] + b4[2*r+0],
                                        acc[2*r+1][py*4+2] + b4[2*r+1],
                                        acc[2*r+0][py*4+3] + b4[2*r+0],
                                        acc[2*r+1][py*4+3] + b4[2*r+1]);
                *(float4*)(orow)     = q0;
                *(float4*)(orow + 4) = q1;
            }
        }
    }
}

// ================= stride2 conv3x3 + 1x1 skip (unchanged, passing) =================
__global__ void down_fused(const float* __restrict__ in3, const float* __restrict__ skin,
                           float* __restrict__ out, int OH, int OW,
                           const float* __restrict__ dw, const float* __restrict__ db,
                           const float* __restrict__ sw, const float* __restrict__ sb)
{
    __shared__ float s_in[8][33][33];
    __shared__ float s_w[4][8][9];
    __shared__ float s_sw[4][8];
    int IH = 2*OH, IW = 2*OW;
    int tx = threadIdx.x, ty = threadIdx.y, tid = ty*16 + tx;
    int x0 = blockIdx.x*16, y0 = blockIdx.y*16;
    int bb = blockIdx.z >> 4;
    int cog = blockIdx.z & 15;
    float acc[4] = {0.f,0.f,0.f,0.f};
    const float* inb = in3 + (size_t)bb*CC*IH*IW;
    const float* skb = skin + (size_t)bb*CC*OH*OW;
    int oy = y0 + ty, ox = x0 + tx;

    for (int c0 = 0; c0 < CC; c0 += 8) {
        for (int i = tid; i < 8*33*33; i += 256) {
            int ci = i / 1089, rem = i % 1089, r = rem / 33, c = rem % 33;
            int y = 2*y0 - 1 + r, x = 2*x0 - 1 + c;
            float v = 0.f;
            if (y >= 0 && y < IH && x >= 0 && x < IW)
                v = inb[(size_t)(c0+ci)*IH*IW + y*IW + x];
            s_in[ci][r][c] = v;
        }
        for (int i = tid; i < 288; i += 256) {
            int col = i / 72, rem = i % 72, ci = rem / 9, k = rem % 9;
            s_w[col][ci][k] = dw[((size_t)(cog*4+col)*CC + c0+ci)*9 + k];
        }
        if (tid < 32) {
            int col = tid >> 3, ci = tid & 7;
            s_sw[col][ci] = sw[(cog*4+col)*CC + c0+ci];
        }
        __syncthreads();
        #pragma unroll
        for (int ci = 0; ci < 8; ci++) {
            float v[9];
            #pragma unroll
            for (int j = 0; j < 9; j++) v[j] = s_in[ci][2*ty + j/3][2*tx + j%3];
            float sv = skb[(size_t)(c0+ci)*OH*OW + oy*OW + ox];
            #pragma unroll
            for (int col = 0; col < 4; col++) {
                float a = acc[col];
                #pragma unroll
                for (int k = 0; k < 9; k++) a += v[k]*s_w[col][ci][k];
                a += sv * s_sw[col][ci];
                acc[col] = a;
            }
        }
        __syncthreads();
    }
    float* ob = out + (size_t)bb*CC*OH*OW;
    #pragma unroll
    for (int col = 0; col < 4; col++) {
        int co = cog*4 + col;
        ob[(size_t)co*OH*OW + oy*OW + ox] = acc[col] + db[co] + sb[co];
    }
}

// ================= weight prep: transpose (fp32) =================
__global__ void prep_wt(const float* __restrict__ w0, const float* __restrict__ w1,
                        const float* __restrict__ w2, const float* __restrict__ w3)
{
    int i = blockIdx.x*256 + threadIdx.x;
    int total = 256*K0P + 3*256*256;
    if (i >= total) return;
    float v;
    if (i < 256*K0P) {
        int n = i / K0P, k = i % K0P;
        v = (k < 260) ? w0[(size_t)k*256 + n] : 0.0f;
    } else {
        int j = i - 256*K0P;
        int l = j / 65536, r = j % 65536;
        int n = r / 256, k = r % 256;
        const float* ws = (l == 0) ? w1 : (l == 1) ? w2 : w3;
        v = ws[(size_t)k*256 + n];
    }
    g_Wt[i] = v;
}

// ================= gather + build X =================
__device__ __forceinline__ int nidx(float cc, float n)
{
    float f = rintf((cc + 1.0f)*(n*0.5f) - 0.5f);
    f = fminf(fmaxf(f, 0.0f), n - 1.0f);
    return (int)f;
}

__global__ void gather_build(const float* __restrict__ coord, const float* __restrict__ cell)
{
    int tid = threadIdx.x;
    int row = blockIdx.x*4 + (tid >> 6);
    int c   = tid & 63;
    int s   = row & 3;
    int bq  = row >> 2;
    int b   = bq >> 14;
    float cy = coord[(size_t)bq*2 + 0];
    float cx = coord[(size_t)bq*2 + 1];
    float vx = (s & 2) ? 1.f : -1.f;
    float vy = (s & 1) ? 1.f : -1.f;
    const float RX = 1.0f/48.0f;
    float sy = fminf(fmaxf(cy + vx*RX + 1e-6f, -1.f + 1e-6f), 1.f - 1e-6f);
    float sx = fminf(fmaxf(cx + vy*RX + 1e-6f, -1.f + 1e-6f), 1.f - 1e-6f);
    int iy0 = nidx(sy, 48.f),  ix0 = nidx(sx, 48.f);
    int iy1 = nidx(sy, 96.f),  ix1 = nidx(sx, 96.f);
    int iy2 = nidx(sy, 192.f), ix2 = nidx(sx, 192.f);
    int iy3 = nidx(sy, 384.f), ix3 = nidx(sx, 384.f);

    float* xr = g_X + (size_t)row*K0P;
    xr[c]       = g_feat [((size_t)(b*CC + c)*48  + iy0)*48  + ix0];
    xr[64 + c]  = g_feat5[((size_t)(b*CC + c)*96  + iy1)*96  + ix1];
    xr[128 + c] = g_feat4[((size_t)(b*CC + c)*192 + iy2)*192 + ix2];
    xr[192 + c] = g_feat3[((size_t)(b*CC + c)*384 + iy3)*384 + ix3];
    if (c == 0) {
        float qcy = -1.f + (2.f*iy0 + 1.f)/48.f;
        float qcx = -1.f + (2.f*ix0 + 1.f)/48.f;
        float ry_ = (cy - qcy)*48.f;
        float rx_ = (cx - qcx)*48.f;
        xr[256] = ry_;
        xr[257] = rx_;
        xr[258] = cell[(size_t)bq*2 + 0]*48.f;
        xr[259] = cell[(size_t)bq*2 + 1]*48.f;
        g_area[row] = fabsf(ry_*rx_) + 1e-9f;
    }
    if (c < 12) xr[260 + c] = 0.0f;   // pad to 272
}

// ================= scalar-FFMA SGEMM, 128x128 tile, 8x8/thread =================
__global__ void __launch_bounds__(256)
gemm_f32(const float* __restrict__ A, const float* __restrict__ Wt,
         const float* __restrict__ bias, float* __restrict__ C, int K)
{
    __shared__ float As[2][8][128];
    __shared__ float Bs[2][8][128];
    int tid = threadIdx.x;
    int tx = tid & 15, ty = tid >> 4;
    int m0 = blockIdx.y*128, n0 = blockIdx.x*128;
    int lrow = tid >> 1, lk = (tid & 1)*4;
    const float* ap = A  + (size_t)(m0 + lrow)*K + lk;
    const float* bp = Wt + (size_t)(n0 + lrow)*K + lk;
    int NK = K >> 3;

    float acc[8][8];
    #pragma unroll
    for (int i = 0; i < 8; i++)
        #pragma unroll
        for (int j = 0; j < 8; j++) acc[i][j] = 0.f;

    float4 av = *(const float4*)ap;
    float4 bv = *(const float4*)bp;

    for (int it = 0; it < NK; it++) {
        int buf = it & 1;
        As[buf][lk+0][lrow] = av.x;
        As[buf][lk+1][lrow] = av.y;
        As[buf][lk+2][lrow] = av.z;
        As[buf][lk+3][lrow] = av.w;
        Bs[buf][lk+0][lrow] = bv.x;
        Bs[buf][lk+1][lrow] = bv.y;
        Bs[buf][lk+2][lrow] = bv.z;
        Bs[buf][lk+3][lrow] = bv.w;
        if (it + 1 < NK) {
            av = *(const float4*)(ap + (it+1)*8);
            bv = *(const float4*)(bp + (it+1)*8);
        }
        __syncthreads();
        #pragma unroll
        for (int kk = 0; kk < 8; kk++) {
            float a[8], b[8];
            *(float4*)(a)   = *(const float4*)&As[buf][kk][ty*4];
            *(float4*)(a+4) = *(const float4*)&As[buf][kk][ty*4 + 64];
            *(float4*)(b)   = *(const float4*)&Bs[buf][kk][tx*4];
            *(float4*)(b+4) = *(const float4*)&Bs[buf][kk][tx*4 + 64];
            #pragma unroll
            for (int i = 0; i < 8; i++)
                #pragma unroll
                for (int j = 0; j < 8; j++)
                    acc[i][j] += a[i]*b[j];
        }
    }

    float bn[8];
    #pragma unroll
    for (int j = 0; j < 8; j++)
        bn[j] = bias[n0 + ((j < 4) ? tx*4 + j : 64 + tx*4 + j - 4)];
    #pragma unroll
    for (int i = 0; i < 8; i++) {
        int m = m0 + ((i < 4) ? ty*4 + i : 64 + ty*4 + i - 4);
        float* cr = C + (size_t)m*HID + n0;
        float4 q0 = make_float4(fmaxf(acc[i][0] + bn[0], 0.f),
                                fmaxf(acc[i][1] + bn[1], 0.f),
                                fmaxf(acc[i][2] + bn[2], 0.f),
                                fmaxf(acc[i][3] + bn[3], 0.f));
        float4 q1 = make_float4(fmaxf(acc[i][4] + bn[4], 0.f),
                                fmaxf(acc[i][5] + bn[5], 0.f),
                                fmaxf(acc[i][6] + bn[6], 0.f),
                                fmaxf(acc[i][7] + bn[7], 0.f));
        *(float4*)(cr + tx*4)      = q0;
        *(float4*)(cr + 64 + tx*4) = q1;
    }
}

// ================= last layer: [M,256]@[256,3]+b =================
__global__ void mlp_last(const float* __restrict__ Hin, const float* __restrict__ W4,
                         const float* __restrict__ b4)
{
    int warp = threadIdx.x >> 5, lane = threadIdx.x & 31;
    int row = blockIdx.x*4 + warp;
    const float* hr = Hin + (size_t)row*HID;
    float a0 = 0.f, a1 = 0.f, a2 = 0.f;
    for (int k = lane; k < HID; k += 32) {
        float h = hr[k];
        a0 += h*W4[k*3 + 0];
        a1 += h*W4[k*3 + 1];
        a2 += h*W4[k*3 + 2];
    }
    #pragma unroll
    for (int o = 16; o; o >>= 1) {
        a0 += __shfl_down_sync(0xffffffffu, a0, o);
        a1 += __shfl_down_sync(0xffffffffu, a1, o);
        a2 += __shfl_down_sync(0xffffffffu, a2, o);
    }
    if (lane == 0) {
        g_P[(size_t)row*3 + 0] = a0 + b4[0];
        g_P[(size_t)row*3 + 1] = a1 + b4[1];
        g_P[(size_t)row*3 + 2] = a2 + b4[2];
    }
}

// ================= ensemble + bilinear border skip =================
__global__ void ensemble(const float* __restrict__ coord, const float* __restrict__ inp,
                         float* __restrict__ out)
{
    int bq = blockIdx.x*256 + threadIdx.x;
    if (bq >= BB*QQ) return;
    int b = bq >> 14;
    float cy = coord[(size_t)bq*2 + 0];
    float cx = coord[(size_t)bq*2 + 1];
    int base = bq*4;
    float a0 = g_area[base+0], a1 = g_area[base+1], a2 = g_area[base+2], a3 = g_area[base+3];
    float inv = 1.0f/(a0 + a1 + a2 + a3);
    float w0 = a3*inv, w1 = a2*inv, w2 = a1*inv, w3 = a0*inv;
    float r[3];
    #pragma unroll
    for (int c = 0; c < 3; c++) {
        r[c] = g_P[(size_t)(base+0)*3 + c]*w0
             + g_P[(size_t)(base+1)*3 + c]*w1
             + g_P[(size_t)(base+2)*3 + c]*w2
             + g_P[(size_t)(base+3)*3 + c]*w3;
    }
    float fy = fminf(fmaxf((cy + 1.f)*24.f - 0.5f, 0.f), 47.f);
    float fx = fminf(fmaxf((cx + 1.f)*24.f - 0.5f, 0.f), 47.f);
    float y0f = floorf(fy), x0f = floorf(fx);
    int y0 = (int)y0f, x0 = (int)x0f;
    float wy = fy - y0f, wx = fx - x0f;
    int y1 = min(y0 + 1, 47), x1 = min(x0 + 1, 47);
    const float* ib = inp + (size_t)b*3*H0*W0;
    #pragma unroll
    for (int ch = 0; ch < 3; ch++) {
        const float* p = ib + ch*H0*W0;
        float v00 = p[y0*48 + x0], v01 = p[y0*48 + x1];
        float v10 = p[y1*48 + x0], v11 = p[y1*48 + x1];
        r[ch] += v00*(1.f - wy)*(1.f - wx) + v01*(1.f - wy)*wx
               + v10*wy*(1.f - wx) + v11*wy*wx;
        out[(size_t)bq*3 + ch] = r[ch];
    }
}

// ================= host launch =================
extern "C" void kernel_launch(void* const* d_in, const int* in_sizes, int n_in,
                              void* d_out, int out_size)
{
    const float* inp     = (const float*)d_in[0];
    const float* coord   = (const float*)d_in[1];
    const float* cell    = (const float*)d_in[2];
    const float* enc_w   = (const float*)d_in[3];
    const float* enc_b   = (const float*)d_in[4];
    const float* up1_w   = (const float*)d_in[5];
    const float* up1_b   = (const float*)d_in[6];
    const float* up2_w   = (const float*)d_in[7];
    const float* up2_b   = (const float*)d_in[8];
    const float* up3_w   = (const float*)d_in[9];
    const float* up3_b   = (const float*)d_in[10];
    const float* skip1_w = (const float*)d_in[11];
    const float* skip1_b = (const float*)d_in[12];
    const float* skip2_w = (const float*)d_in[13];
    const float* skip2_b = (const float*)d_in[14];
    const float* down4_w = (const float*)d_in[15];
    const float* down4_b = (const float*)d_in[16];
    const float* down5_w = (const float*)d_in[17];
    const float* down5_b = (const float*)d_in[18];
    const float* mlp_w0  = (const float*)d_in[19];
    const float* mlp_b0  = (const float*)d_in[20];
    const float* mlp_w1  = (const float*)d_in[21];
    const float* mlp_b1  = (const float*)d_in[22];
    const float* mlp_w2  = (const float*)d_in[23];
    const float* mlp_b2  = (const float*)d_in[24];
    const float* mlp_w3  = (const float*)d_in[25];
    const float* mlp_b3  = (const float*)d_in[26];
    const float* mlp_w4  = (const float*)d_in[27];
    const float* mlp_b4  = (const float*)d_in[28];
    float* out = (float*)d_out;

    float *p_feat, *p_feat1, *p_feat2, *p_feat3, *p_feat4, *p_feat5;
    float *p_X, *p_H0, *p_H1, *p_Wt;
    cudaGetSymbolAddress((void**)&p_feat,  g_feat);
    cudaGetSymbolAddress((void**)&p_feat1, g_feat1);
    cudaGetSymbolAddress((void**)&p_feat2, g_feat2);
    cudaGetSymbolAddress((void**)&p_feat3, g_feat3);
    cudaGetSymbolAddress((void**)&p_feat4, g_feat4);
    cudaGetSymbolAddress((void**)&p_feat5, g_feat5);
    cudaGetSymbolAddress((void**)&p_X,  g_X);
    cudaGetSymbolAddress((void**)&p_H0, g_H0b);
    cudaGetSymbolAddress((void**)&p_H1, g_H1b);
    cudaGetSymbolAddress((void**)&p_Wt, g_Wt);

    // weight prep (independent of convs)
    {
        int total = 256*K0P + 3*256*256;
        prep_wt<<<(total + 255)/256, 256>>>(mlp_w0, mlp_w1, mlp_w2, mlp_w3);
    }
    // encoder + pyramid
    {
        int total = BB*CC*H0*W0;
        enc_conv<<<(total + 255)/256, 256>>>(inp, enc_w, enc_b);
        up_conv_ps3<<<dim3(2, 2, BB*64), 128>>>(p_feat,  p_feat1, 48, 48,  up1_w, up1_b);
        up_conv_ps3<<<dim3(3, 3, BB*64), 128>>>(p_feat1, p_feat2, 96, 96,  up2_w, up2_b);
        up_conv_ps3<<<dim3(6, 6, BB*64), 128>>>(p_feat2, p_feat3, 192,192, up3_w, up3_b);
        dim3 blk(16,16);
        down_fused<<<dim3(12, 12, BB*16), blk>>>(p_feat3, p_feat2, p_feat4, 192, 192,
                                                 down4_w, down4_b, skip1_w, skip1_b);
        down_fused<<<dim3(6,  6,  BB*16), blk>>>(p_feat4, p_feat1, p_feat5, 96, 96,
                                                 down5_w, down5_b, skip2_w, skip2_b);
    }
    // gather + build X (fp32, padded to 272)
    gather_build<<<MROWS/4, 256>>>(coord, cell);

    // MLP hidden layers: scalar-FFMA 128x128 GEMM
    {
        dim3 grid(HID/128, MROWS/128);   // (2, 2048)
        const float* W1 = p_Wt + 256*K0P;
        const float* W2 = W1 + 65536;
        const float* W3 = W2 + 65536;
        gemm_f32<<<grid, 256>>>(p_X,  p_Wt, mlp_b0, p_H0, K0P);
        gemm_f32<<<grid, 256>>>(p_H0, W1,   mlp_b1, p_H1, 256);
        gemm_f32<<<grid, 256>>>(p_H1, W2,   mlp_b2, p_H0, 256);
        gemm_f32<<<grid, 256>>>(p_H0, W3,   mlp_b3, p_H1, 256);
    }
    // last layer + ensemble
    mlp_last<<<MROWS/4, 128>>>(p_H1, mlp_w4, mlp_b4);
    ensemble<<<(BB*QQ + 255)/256, 256>>>(coord, inp, out);
}